// round 1
// baseline (speedup 1.0000x reference)
#include <cuda_runtime.h>
#include <math.h>
#include <stdint.h>

#define Lc 6
#define Bc 16
#define Tc 512
#define Dc 512
#define Hc 8
#define Ac 64
#define Fc 2048
#define Ec 200000
#define BIASDIM 4

// ---------------- scratch (device globals; no allocations allowed) ----------
__device__ float g_x[Bc*Tc*Dc];
__device__ float g_h[Bc*Tc*Dc];
__device__ float g_q[Bc*Tc*Dc];
__device__ float g_k[Bc*Tc*Dc];
__device__ float g_v[Bc*Tc*Dc];
__device__ float g_ctx[Bc*Tc*Dc];
__device__ float g_ksum[Bc*Tc*Hc];
__device__ float g_dense[Bc*Tc*Tc];
__device__ float g_alpha[(size_t)Bc*Hc*Tc*Tc];
__device__ float g_ffh[Bc*Tc*Fc];

// ---------------- embedding + positional encoding ---------------------------
__global__ __launch_bounds__(512) void embed_pe_kernel(
    const int* __restrict__ tokens, const float* __restrict__ embed)
{
    int bt = blockIdx.x;           // 0..B*T-1
    int d  = threadIdx.x;          // 0..511
    int t  = bt % Tc;
    int tok = tokens[bt];
    float val = embed[(size_t)tok * Dc + d] * 22.62741699796952f; // sqrt(512)
    float expo  = (2.0f * (float)(d >> 1)) / (float)Dc;
    float denom = powf(10000.0f, expo);
    float angle = (float)t / denom;
    val += ((d & 1) == 0) ? sinf(angle) : cosf(angle);
    g_x[(size_t)bt * Dc + d] = val;
}

// ---------------- layernorm (block per token, D=512) -------------------------
__global__ __launch_bounds__(256) void layernorm_kernel(
    const float* __restrict__ in, const float* __restrict__ gamma,
    const float* __restrict__ beta, float* __restrict__ out)
{
    __shared__ float red[256];
    size_t base = (size_t)blockIdx.x * Dc;
    int tid = threadIdx.x;
    float v0 = in[base + tid];
    float v1 = in[base + tid + 256];
    red[tid] = v0 + v1;
    __syncthreads();
    #pragma unroll
    for (int s = 128; s > 0; s >>= 1) {
        if (tid < s) red[tid] += red[tid + s];
        __syncthreads();
    }
    float mu = red[0] * (1.0f / Dc);
    __syncthreads();
    float d0 = v0 - mu, d1 = v1 - mu;
    red[tid] = d0 * d0 + d1 * d1;
    __syncthreads();
    #pragma unroll
    for (int s = 128; s > 0; s >>= 1) {
        if (tid < s) red[tid] += red[tid + s];
        __syncthreads();
    }
    float rstd = rsqrtf(red[0] * (1.0f / Dc) + 1e-3f);
    out[base + tid]       = d0 * rstd * gamma[tid]       + beta[tid];
    out[base + tid + 256] = d1 * rstd * gamma[tid + 256] + beta[tid + 256];
}

// ---------------- generic NN SGEMM: C[M,N] = A[M,K] @ B[K,N] (+epilogue) ----
// grid: (N/64, M/64), block 256. Row-major, dims multiples of 64/16.
__global__ __launch_bounds__(256) void gemm_nn_kernel(
    const float* __restrict__ A, const float* __restrict__ B,
    const float* __restrict__ bias, const float* __restrict__ resid,
    float* __restrict__ C, int M, int N, int K, int do_relu)
{
    __shared__ float As[16][64];
    __shared__ float Bs[16][64];
    int tid = threadIdx.x;
    int tx = tid & 15, ty = tid >> 4;
    int row0 = blockIdx.y * 64;
    int col0 = blockIdx.x * 64;

    float acc[4][4] = {};
    for (int k0 = 0; k0 < K; k0 += 16) {
        {   // A tile 64x16, store transposed
            int r = tid >> 2;
            int c = (tid & 3) << 2;
            float4 va = *(const float4*)(A + (size_t)(row0 + r) * K + k0 + c);
            As[c + 0][r] = va.x; As[c + 1][r] = va.y;
            As[c + 2][r] = va.z; As[c + 3][r] = va.w;
        }
        {   // B tile 16x64
            int r = tid >> 4;
            int c = (tid & 15) << 2;
            *(float4*)&Bs[r][c] =
                *(const float4*)(B + (size_t)(k0 + r) * N + col0 + c);
        }
        __syncthreads();
        #pragma unroll
        for (int kk = 0; kk < 16; kk++) {
            float4 a = *(const float4*)&As[kk][ty * 4];
            float4 b = *(const float4*)&Bs[kk][tx * 4];
            float av[4] = {a.x, a.y, a.z, a.w};
            float bv[4] = {b.x, b.y, b.z, b.w};
            #pragma unroll
            for (int i = 0; i < 4; i++)
                #pragma unroll
                for (int j = 0; j < 4; j++)
                    acc[i][j] += av[i] * bv[j];
        }
        __syncthreads();
    }
    #pragma unroll
    for (int i = 0; i < 4; i++) {
        int m = row0 + ty * 4 + i;
        #pragma unroll
        for (int j = 0; j < 4; j++) {
            int n = col0 + tx * 4 + j;
            float v = acc[i][j];
            if (bias)  v += bias[n];
            if (do_relu) v = fmaxf(v, 0.0f);
            if (resid) v += resid[(size_t)m * N + n];
            C[(size_t)m * N + n] = v;
        }
    }
}

// ---------------- ksum[b,t,h] = sum_a k[b,t,h,a] ----------------------------
__global__ __launch_bounds__(256) void ksum_kernel(void)
{
    int i = blockIdx.x * blockDim.x + threadIdx.x;
    if (i >= Bc * Tc * Hc) return;
    const float* p = g_k + (size_t)(i >> 3) * Dc + (i & 7) * Ac;
    float s = 0.0f;
    #pragma unroll
    for (int a = 0; a < Ac; a += 4) {
        float4 w = *(const float4*)(p + a);
        s += w.x + w.y + w.z + w.w;
    }
    g_ksum[i] = s;
}

// ---------------- zero dense bias map ---------------------------------------
__global__ __launch_bounds__(256) void zero_kernel(float* __restrict__ p, int n4)
{
    int i = blockIdx.x * blockDim.x + threadIdx.x;
    if (i < n4) ((float4*)p)[i] = make_float4(0.f, 0.f, 0.f, 0.f);
}

// ---------------- sparse edge bias scatter ----------------------------------
__global__ __launch_bounds__(256) void bias_scatter_kernel(
    const int* __restrict__ ab, const float* __restrict__ be_l,
    const float* __restrict__ bs_l)
{
    __shared__ float evtab[BIASDIM];
    if (threadIdx.x < BIASDIM) {
        float s = 0.0f;
        #pragma unroll
        for (int a = 0; a < Ac; a++)
            s += be_l[threadIdx.x * Ac + a] * bs_l[a];
        evtab[threadIdx.x] = s;
    }
    __syncthreads();
    int e = blockIdx.x * blockDim.x + threadIdx.x;
    if (e >= Ec) return;
    int ty = ab[e * 4 + 0];
    int b  = ab[e * 4 + 1];
    int q  = ab[e * 4 + 2];
    int k  = ab[e * 4 + 3];
    atomicAdd(&g_dense[((size_t)b * Tc + q) * Tc + k], evtab[ty]);
}

// ---------------- attention scores (batched NT) + bias + scale + mask -------
// grid (T/64, T/64, B*H): x = k-tile, y = q-tile, z = b*H + h
__global__ __launch_bounds__(256) void attn_score_kernel(
    const float* __restrict__ masks)
{
    __shared__ float Qs[16][64];
    __shared__ float Ks[16][64];
    int z = blockIdx.z;
    int b = z >> 3, h = z & 7;
    int tid = threadIdx.x;
    int tx = tid & 15, ty = tid >> 4;
    int q0 = blockIdx.y * 64;
    int c0 = blockIdx.x * 64;

    const float* qb = g_q + (size_t)b * Tc * Dc + h * Ac;
    const float* kb = g_k + (size_t)b * Tc * Dc + h * Ac;

    float acc[4][4] = {};
    for (int a0 = 0; a0 < Ac; a0 += 16) {
        {
            int r = tid >> 2;
            int c = (tid & 3) << 2;
            float4 va = *(const float4*)(qb + (size_t)(q0 + r) * Dc + a0 + c);
            Qs[c + 0][r] = va.x; Qs[c + 1][r] = va.y;
            Qs[c + 2][r] = va.z; Qs[c + 3][r] = va.w;
            float4 vb = *(const float4*)(kb + (size_t)(c0 + r) * Dc + a0 + c);
            Ks[c + 0][r] = vb.x; Ks[c + 1][r] = vb.y;
            Ks[c + 2][r] = vb.z; Ks[c + 3][r] = vb.w;
        }
        __syncthreads();
        #pragma unroll
        for (int kk = 0; kk < 16; kk++) {
            float4 a = *(const float4*)&Qs[kk][ty * 4];
            float4 bq = *(const float4*)&Ks[kk][tx * 4];
            float av[4] = {a.x, a.y, a.z, a.w};
            float bv[4] = {bq.x, bq.y, bq.z, bq.w};
            #pragma unroll
            for (int i = 0; i < 4; i++)
                #pragma unroll
                for (int j = 0; j < 4; j++)
                    acc[i][j] += av[i] * bv[j];
        }
        __syncthreads();
    }
    #pragma unroll
    for (int i = 0; i < 4; i++) {
        int qg = q0 + ty * 4 + i;
        #pragma unroll
        for (int j = 0; j < 4; j++) {
            int kg = c0 + tx * 4 + j;
            float dv = g_dense[((size_t)b * Tc + qg) * Tc + kg];
            float ks = g_ksum[((size_t)b * Tc + kg) * Hc + h];
            float val = (acc[i][j] + dv * ks) * 0.125f;  // rsqrt(64)
            float m = masks[((size_t)b * Tc + qg) * Tc + kg];
            val = val * m + (1.0f - ceilf(m)) * (-3.402823466e38f);
            g_alpha[(((size_t)z * Tc) + qg) * Tc + kg] = val;
        }
    }
}

// ---------------- softmax over last axis (rows of 512) ----------------------
__global__ __launch_bounds__(128) void softmax_kernel(void)
{
    __shared__ float red[128];
    size_t base = (size_t)blockIdx.x * Tc;
    int tid = threadIdx.x;
    float4 v = *(float4*)(g_alpha + base + tid * 4);
    float m = fmaxf(fmaxf(v.x, v.y), fmaxf(v.z, v.w));
    red[tid] = m;
    __syncthreads();
    #pragma unroll
    for (int s = 64; s > 0; s >>= 1) {
        if (tid < s) red[tid] = fmaxf(red[tid], red[tid + s]);
        __syncthreads();
    }
    m = red[0];
    __syncthreads();
    float e0 = expf(v.x - m), e1 = expf(v.y - m);
    float e2 = expf(v.z - m), e3 = expf(v.w - m);
    red[tid] = e0 + e1 + e2 + e3;
    __syncthreads();
    #pragma unroll
    for (int s = 64; s > 0; s >>= 1) {
        if (tid < s) red[tid] += red[tid + s];
        __syncthreads();
    }
    float inv = 1.0f / red[0];
    *(float4*)(g_alpha + base + tid * 4) =
        make_float4(e0 * inv, e1 * inv, e2 * inv, e3 * inv);
}

// ---------------- context (batched NN): ctx = alpha @ V ---------------------
// grid (T/64, B*H): x = q-tile, y = z = b*H + h
__global__ __launch_bounds__(256) void attn_ctx_kernel(void)
{
    __shared__ float As[16][64];
    __shared__ float Bs[16][64];
    int z = blockIdx.y;
    int b = z >> 3, h = z & 7;
    int tid = threadIdx.x;
    int tx = tid & 15, ty = tid >> 4;
    int q0 = blockIdx.x * 64;

    const float* ap = g_alpha + (size_t)z * Tc * Tc;
    const float* vb = g_v + (size_t)b * Tc * Dc + h * Ac;

    float acc[4][4] = {};
    for (int k0 = 0; k0 < Tc; k0 += 16) {
        {
            int r = tid >> 2;
            int c = (tid & 3) << 2;
            float4 va = *(const float4*)(ap + (size_t)(q0 + r) * Tc + k0 + c);
            As[c + 0][r] = va.x; As[c + 1][r] = va.y;
            As[c + 2][r] = va.z; As[c + 3][r] = va.w;
        }
        {
            int r = tid >> 4;
            int c = (tid & 15) << 2;
            *(float4*)&Bs[r][c] =
                *(const float4*)(vb + (size_t)(k0 + r) * Dc + c);
        }
        __syncthreads();
        #pragma unroll
        for (int kk = 0; kk < 16; kk++) {
            float4 a = *(const float4*)&As[kk][ty * 4];
            float4 bq = *(const float4*)&Bs[kk][tx * 4];
            float av[4] = {a.x, a.y, a.z, a.w};
            float bv[4] = {bq.x, bq.y, bq.z, bq.w};
            #pragma unroll
            for (int i = 0; i < 4; i++)
                #pragma unroll
                for (int j = 0; j < 4; j++)
                    acc[i][j] += av[i] * bv[j];
        }
        __syncthreads();
    }
    #pragma unroll
    for (int i = 0; i < 4; i++) {
        int qg = q0 + ty * 4 + i;
        #pragma unroll
        for (int j = 0; j < 4; j++) {
            int a = tx * 4 + j;
            g_ctx[((size_t)b * Tc + qg) * Dc + h * Ac + a] = acc[i][j];
        }
    }
}

// ---------------- host driver -----------------------------------------------
extern "C" void kernel_launch(void* const* d_in, const int* in_sizes, int n_in,
                              void* d_out, int out_size)
{
    const int*   tokens = (const int*)  d_in[0];
    const float* masks  = (const float*)d_in[1];
    const int*   ab     = (const int*)  d_in[2];
    const float* embed  = (const float*)d_in[3];
    const float* Wq     = (const float*)d_in[4];
    const float* Wk     = (const float*)d_in[5];
    const float* Wv     = (const float*)d_in[6];
    const float* Wo     = (const float*)d_in[7];
    const float* be     = (const float*)d_in[8];
    const float* bs     = (const float*)d_in[9];
    const float* ln_g   = (const float*)d_in[10];
    const float* ln_b   = (const float*)d_in[11];
    const float* ff1w   = (const float*)d_in[12];
    const float* ff1b   = (const float*)d_in[13];
    const float* ff2w   = (const float*)d_in[14];
    const float* ff2b   = (const float*)d_in[15];
    const float* lng    = (const float*)d_in[16];
    const float* lnb    = (const float*)d_in[17];
    float* out = (float*)d_out;

    float *x, *h, *q, *k, *v, *ctx, *dense, *ffh;
    cudaGetSymbolAddress((void**)&x,     g_x);
    cudaGetSymbolAddress((void**)&h,     g_h);
    cudaGetSymbolAddress((void**)&q,     g_q);
    cudaGetSymbolAddress((void**)&k,     g_k);
    cudaGetSymbolAddress((void**)&v,     g_v);
    cudaGetSymbolAddress((void**)&ctx,   g_ctx);
    cudaGetSymbolAddress((void**)&dense, g_dense);
    cudaGetSymbolAddress((void**)&ffh,   g_ffh);

    const int MT = Bc * Tc;                 // 8192 tokens

    embed_pe_kernel<<<MT, 512>>>(tokens, embed);

    for (int l = 0; l < Lc; l++) {
        const float* Wq_l  = Wq + (size_t)l * Dc * Dc;
        const float* Wk_l  = Wk + (size_t)l * Dc * Dc;
        const float* Wv_l  = Wv + (size_t)l * Dc * Dc;
        const float* Wo_l  = Wo + (size_t)l * Dc * Dc;
        const float* be_l  = be + (size_t)l * BIASDIM * Ac;
        const float* bs_l  = bs + (size_t)l * Ac;
        const float* ln1g  = ln_g + (size_t)l * 2 * Dc;
        const float* ln1b  = ln_b + (size_t)l * 2 * Dc;
        const float* ln2g  = ln1g + Dc;
        const float* ln2b  = ln1b + Dc;
        const float* f1w   = ff1w + (size_t)l * Dc * Fc;
        const float* f1b   = ff1b + (size_t)l * Fc;
        const float* f2w   = ff2w + (size_t)l * Fc * Dc;
        const float* f2b   = ff2b + (size_t)l * Dc;

        // LN1
        layernorm_kernel<<<MT, 256>>>(x, ln1g, ln1b, h);

        // QKV projections
        gemm_nn_kernel<<<dim3(Dc/64, MT/64), 256>>>(h, Wq_l, nullptr, nullptr, q, MT, Dc, Dc, 0);
        gemm_nn_kernel<<<dim3(Dc/64, MT/64), 256>>>(h, Wk_l, nullptr, nullptr, k, MT, Dc, Dc, 0);
        gemm_nn_kernel<<<dim3(Dc/64, MT/64), 256>>>(h, Wv_l, nullptr, nullptr, v, MT, Dc, Dc, 0);

        // ksum over a
        ksum_kernel<<<(Bc*Tc*Hc + 255)/256, 256>>>();

        // dense bias map: zero + scatter
        zero_kernel<<<(Bc*Tc*Tc/4 + 255)/256, 256>>>(dense, Bc*Tc*Tc/4);
        bias_scatter_kernel<<<(Ec + 255)/256, 256>>>(ab, be_l, bs_l);

        // scores + bias + scale + mask, then softmax
        attn_score_kernel<<<dim3(Tc/64, Tc/64, Bc*Hc), 256>>>(masks);
        softmax_kernel<<<Bc*Hc*Tc, 128>>>();

        // context, output projection + residual
        attn_ctx_kernel<<<dim3(Tc/64, Bc*Hc), 256>>>();
        gemm_nn_kernel<<<dim3(Dc/64, MT/64), 256>>>(ctx, Wo_l, nullptr, x, x, MT, Dc, Dc, 0);

        // LN2 + FFN + residual
        layernorm_kernel<<<MT, 256>>>(x, ln2g, ln2b, h);
        gemm_nn_kernel<<<dim3(Fc/64, MT/64), 256>>>(h, f1w, f1b, nullptr, ffh, MT, Fc, Dc, 1);
        gemm_nn_kernel<<<dim3(Dc/64, MT/64), 256>>>(ffh, f2w, f2b, x, x, MT, Dc, Fc, 0);
    }

    // final layernorm -> output
    layernorm_kernel<<<MT, 256>>>(x, lng, lnb, out);
}

// round 2
// speedup vs baseline: 1.3111x; 1.3111x over previous
#include <cuda_runtime.h>
#include <math.h>
#include <stdint.h>

#define Lc 6
#define Bc 16
#define Tc 512
#define Dc 512
#define Hc 8
#define Ac 64
#define Fc 2048
#define Ec 200000
#define BIASDIM 4

// ---------------- scratch (device globals; no allocations allowed) ----------
__device__ float g_x[Bc*Tc*Dc];
__device__ float g_h[Bc*Tc*Dc];
__device__ float g_q[Bc*Tc*Dc];
__device__ float g_k[Bc*Tc*Dc];
__device__ float g_v[Bc*Tc*Dc];
__device__ float g_ctx[Bc*Tc*Dc];
__device__ float g_ksum[Bc*Hc*Tc];                  // [b,h,t] (transposed!)
__device__ float g_dense[Bc*Tc*Tc];
__device__ float g_alpha[(size_t)Bc*Hc*Tc*Tc];
__device__ float g_ffh[Bc*Tc*Fc];

// ---------------- embedding + positional encoding ---------------------------
__global__ __launch_bounds__(512) void embed_pe_kernel(
    const int* __restrict__ tokens, const float* __restrict__ embed)
{
    int bt = blockIdx.x;
    int d  = threadIdx.x;
    int t  = bt % Tc;
    int tok = tokens[bt];
    float val = embed[(size_t)tok * Dc + d] * 22.62741699796952f; // sqrt(512)
    float expo  = (2.0f * (float)(d >> 1)) / (float)Dc;
    float denom = powf(10000.0f, expo);
    float angle = (float)t / denom;
    val += ((d & 1) == 0) ? sinf(angle) : cosf(angle);
    g_x[(size_t)bt * Dc + d] = val;
}

// ---------------- layernorm (block per token, D=512) -------------------------
__global__ __launch_bounds__(256) void layernorm_kernel(
    const float* __restrict__ in, const float* __restrict__ gamma,
    const float* __restrict__ beta, float* __restrict__ out)
{
    __shared__ float red[256];
    size_t base = (size_t)blockIdx.x * Dc;
    int tid = threadIdx.x;
    float v0 = in[base + tid];
    float v1 = in[base + tid + 256];
    red[tid] = v0 + v1;
    __syncthreads();
    #pragma unroll
    for (int s = 128; s > 0; s >>= 1) {
        if (tid < s) red[tid] += red[tid + s];
        __syncthreads();
    }
    float mu = red[0] * (1.0f / Dc);
    __syncthreads();
    float d0 = v0 - mu, d1 = v1 - mu;
    red[tid] = d0 * d0 + d1 * d1;
    __syncthreads();
    #pragma unroll
    for (int s = 128; s > 0; s >>= 1) {
        if (tid < s) red[tid] += red[tid + s];
        __syncthreads();
    }
    float rstd = rsqrtf(red[0] * (1.0f / Dc) + 1e-3f);
    out[base + tid]       = d0 * rstd * gamma[tid]       + beta[tid];
    out[base + tid + 256] = d1 * rstd * gamma[tid + 256] + beta[tid + 256];
}

// ---------------- 128x128 SGEMM, 8x8 microtile, register prefetch -----------
// C[M,N] = A[M,K] @ B[K,N] (+bias, relu, residual). grid (N/128, M/128), 256 thr.
__global__ __launch_bounds__(256) void gemm_nn_128(
    const float* __restrict__ A, const float* __restrict__ B,
    const float* __restrict__ bias, const float* __restrict__ resid,
    float* __restrict__ C, int M, int N, int K, int do_relu)
{
    __shared__ __align__(16) float As[8][128];
    __shared__ __align__(16) float Bs[8][128];
    int t = threadIdx.x;
    int row0 = blockIdx.y * 128, col0 = blockIdx.x * 128;

    int ar = t >> 1, ac = (t & 1) * 4;     // A loader: row ar, cols ac..ac+3
    int br = t >> 5, bc = (t & 31) * 4;    // B loader: row br, cols bc..bc+3
    const float* Aptr = A + (size_t)(row0 + ar) * K + ac;
    const float* Bptr = B + (size_t)br * N + col0 + bc;

    int tx = t & 15, ty = t >> 4;
    float acc[8][8] = {};

    float4 pa = *(const float4*)Aptr;
    float4 pb = *(const float4*)Bptr;

    for (int k0 = 0; k0 < K; k0 += 8) {
        As[ac + 0][ar] = pa.x; As[ac + 1][ar] = pa.y;
        As[ac + 2][ar] = pa.z; As[ac + 3][ar] = pa.w;
        *(float4*)&Bs[br][bc] = pb;
        __syncthreads();
        if (k0 + 8 < K) {
            pa = *(const float4*)(Aptr + k0 + 8);
            pb = *(const float4*)(Bptr + (size_t)(k0 + 8) * N);
        }
        #pragma unroll
        for (int kk = 0; kk < 8; kk++) {
            float4 a0 = *(const float4*)&As[kk][ty * 4];
            float4 a1 = *(const float4*)&As[kk][ty * 4 + 64];
            float4 b0 = *(const float4*)&Bs[kk][tx * 4];
            float4 b1 = *(const float4*)&Bs[kk][tx * 4 + 64];
            float av[8] = {a0.x,a0.y,a0.z,a0.w,a1.x,a1.y,a1.z,a1.w};
            float bv[8] = {b0.x,b0.y,b0.z,b0.w,b1.x,b1.y,b1.z,b1.w};
            #pragma unroll
            for (int i = 0; i < 8; i++)
                #pragma unroll
                for (int j = 0; j < 8; j++)
                    acc[i][j] += av[i] * bv[j];
        }
        __syncthreads();
    }
    #pragma unroll
    for (int i = 0; i < 8; i++) {
        int m = row0 + ty * 4 + (i & 3) + (i >> 2) * 64;
        #pragma unroll
        for (int jh = 0; jh < 2; jh++) {
            int n = col0 + tx * 4 + jh * 64;
            float4 v;
            v.x = acc[i][jh*4+0]; v.y = acc[i][jh*4+1];
            v.z = acc[i][jh*4+2]; v.w = acc[i][jh*4+3];
            if (bias) {
                v.x += bias[n+0]; v.y += bias[n+1];
                v.z += bias[n+2]; v.w += bias[n+3];
            }
            if (do_relu) {
                v.x = fmaxf(v.x, 0.f); v.y = fmaxf(v.y, 0.f);
                v.z = fmaxf(v.z, 0.f); v.w = fmaxf(v.w, 0.f);
            }
            if (resid) {
                float4 r = *(const float4*)(resid + (size_t)m * N + n);
                v.x += r.x; v.y += r.y; v.z += r.z; v.w += r.w;
            }
            *(float4*)(C + (size_t)m * N + n) = v;
        }
    }
}

// ---------------- ksum[b,h,t] = sum_a k[b,t,h,a]  (transposed layout) -------
__global__ __launch_bounds__(256) void ksum_kernel(void)
{
    int i = blockIdx.x * blockDim.x + threadIdx.x;   // i = (b*T + t)*H + h
    if (i >= Bc * Tc * Hc) return;
    int bt = i >> 3, h = i & 7;
    int b = bt / Tc, tt = bt % Tc;
    const float* p = g_k + (size_t)bt * Dc + h * Ac;
    float s = 0.0f;
    #pragma unroll
    for (int a = 0; a < Ac; a += 4) {
        float4 w = *(const float4*)(p + a);
        s += w.x + w.y + w.z + w.w;
    }
    g_ksum[((size_t)b * Hc + h) * Tc + tt] = s;
}

// ---------------- zero dense bias map ---------------------------------------
__global__ __launch_bounds__(256) void zero_kernel(float* __restrict__ p, int n4)
{
    int i = blockIdx.x * blockDim.x + threadIdx.x;
    if (i < n4) ((float4*)p)[i] = make_float4(0.f, 0.f, 0.f, 0.f);
}

// ---------------- sparse edge bias scatter ----------------------------------
__global__ __launch_bounds__(256) void bias_scatter_kernel(
    const int* __restrict__ ab, const float* __restrict__ be_l,
    const float* __restrict__ bs_l)
{
    __shared__ float evtab[BIASDIM];
    if (threadIdx.x < BIASDIM) {
        float s = 0.0f;
        #pragma unroll
        for (int a = 0; a < Ac; a++)
            s += be_l[threadIdx.x * Ac + a] * bs_l[a];
        evtab[threadIdx.x] = s;
    }
    __syncthreads();
    int e = blockIdx.x * blockDim.x + threadIdx.x;
    if (e >= Ec) return;
    int ty = ab[e * 4 + 0];
    int b  = ab[e * 4 + 1];
    int q  = ab[e * 4 + 2];
    int k  = ab[e * 4 + 3];
    atomicAdd(&g_dense[((size_t)b * Tc + q) * Tc + k], evtab[ty]);
}

// ---------------- attention scores: 128x128 tiles, K=64 ---------------------
// grid (T/128, T/128, B*H). alpha[z,q,k] = (q.kT + dense*ksum)*scale, masked.
__global__ __launch_bounds__(256) void attn_score_kernel(
    const float* __restrict__ masks)
{
    __shared__ __align__(16) float Qs[8][128];
    __shared__ __align__(16) float Ks[8][128];
    int z = blockIdx.z;
    int b = z >> 3, h = z & 7;
    int t = threadIdx.x;
    int q0 = blockIdx.y * 128, c0 = blockIdx.x * 128;

    const float* qb = g_q + (size_t)b * Tc * Dc + h * Ac;
    const float* kb = g_k + (size_t)b * Tc * Dc + h * Ac;

    int ar = t >> 1, ac = (t & 1) * 4;       // both operands load transposed
    const float* Qptr = qb + (size_t)(q0 + ar) * Dc + ac;
    const float* Kptr = kb + (size_t)(c0 + ar) * Dc + ac;

    int tx = t & 15, ty = t >> 4;
    float acc[8][8] = {};

    float4 pq = *(const float4*)Qptr;
    float4 pk = *(const float4*)Kptr;

    for (int a0 = 0; a0 < Ac; a0 += 8) {
        Qs[ac + 0][ar] = pq.x; Qs[ac + 1][ar] = pq.y;
        Qs[ac + 2][ar] = pq.z; Qs[ac + 3][ar] = pq.w;
        Ks[ac + 0][ar] = pk.x; Ks[ac + 1][ar] = pk.y;
        Ks[ac + 2][ar] = pk.z; Ks[ac + 3][ar] = pk.w;
        __syncthreads();
        if (a0 + 8 < Ac) {
            pq = *(const float4*)(Qptr + a0 + 8);
            pk = *(const float4*)(Kptr + a0 + 8);
        }
        #pragma unroll
        for (int kk = 0; kk < 8; kk++) {
            float4 a0v = *(const float4*)&Qs[kk][ty * 4];
            float4 a1v = *(const float4*)&Qs[kk][ty * 4 + 64];
            float4 b0v = *(const float4*)&Ks[kk][tx * 4];
            float4 b1v = *(const float4*)&Ks[kk][tx * 4 + 64];
            float av[8] = {a0v.x,a0v.y,a0v.z,a0v.w,a1v.x,a1v.y,a1v.z,a1v.w};
            float bv[8] = {b0v.x,b0v.y,b0v.z,b0v.w,b1v.x,b1v.y,b1v.z,b1v.w};
            #pragma unroll
            for (int i = 0; i < 8; i++)
                #pragma unroll
                for (int j = 0; j < 8; j++)
                    acc[i][j] += av[i] * bv[j];
        }
        __syncthreads();
    }

    const float* ksrow = g_ksum + ((size_t)b * Hc + h) * Tc;
    #pragma unroll
    for (int i = 0; i < 8; i++) {
        int qg = q0 + ty * 4 + (i & 3) + (i >> 2) * 64;
        size_t drow = ((size_t)b * Tc + qg) * Tc;
        size_t orow = ((size_t)z * Tc + qg) * Tc;
        #pragma unroll
        for (int jh = 0; jh < 2; jh++) {
            int n = c0 + tx * 4 + jh * 64;
            float4 dv = *(const float4*)(g_dense + drow + n);
            float4 ks = *(const float4*)(ksrow + n);
            float4 mk = *(const float4*)(masks + drow + n);
            float r[4];
            float aa[4] = {acc[i][jh*4+0], acc[i][jh*4+1],
                           acc[i][jh*4+2], acc[i][jh*4+3]};
            float dd[4] = {dv.x, dv.y, dv.z, dv.w};
            float kk2[4] = {ks.x, ks.y, ks.z, ks.w};
            float mm[4] = {mk.x, mk.y, mk.z, mk.w};
            #pragma unroll
            for (int j = 0; j < 4; j++) {
                float val = (aa[j] + dd[j] * kk2[j]) * 0.125f;
                r[j] = val * mm[j] + (1.0f - ceilf(mm[j])) * (-3.402823466e38f);
            }
            *(float4*)(g_alpha + orow + n) = make_float4(r[0], r[1], r[2], r[3]);
        }
    }
}

// ---------------- softmax over last axis (rows of 512) ----------------------
__global__ __launch_bounds__(128) void softmax_kernel(void)
{
    __shared__ float red[128];
    size_t base = (size_t)blockIdx.x * Tc;
    int tid = threadIdx.x;
    float4 v = *(float4*)(g_alpha + base + tid * 4);
    float m = fmaxf(fmaxf(v.x, v.y), fmaxf(v.z, v.w));
    red[tid] = m;
    __syncthreads();
    #pragma unroll
    for (int s = 64; s > 0; s >>= 1) {
        if (tid < s) red[tid] = fmaxf(red[tid], red[tid + s]);
        __syncthreads();
    }
    m = red[0];
    __syncthreads();
    float e0 = expf(v.x - m), e1 = expf(v.y - m);
    float e2 = expf(v.z - m), e3 = expf(v.w - m);
    red[tid] = e0 + e1 + e2 + e3;
    __syncthreads();
    #pragma unroll
    for (int s = 64; s > 0; s >>= 1) {
        if (tid < s) red[tid] += red[tid + s];
        __syncthreads();
    }
    float inv = 1.0f / red[0];
    *(float4*)(g_alpha + base + tid * 4) =
        make_float4(e0 * inv, e1 * inv, e2 * inv, e3 * inv);
}

// ---------------- context: ctx = alpha @ V, tile 128x64, 128 threads --------
// grid (T/128, B*H)
__global__ __launch_bounds__(128) void attn_ctx_kernel(void)
{
    __shared__ __align__(16) float As[8][128];
    __shared__ __align__(16) float Bs[8][64];
    int z = blockIdx.y;
    int b = z >> 3, h = z & 7;
    int t = threadIdx.x;
    int q0 = blockIdx.x * 128;

    const float* ap = g_alpha + (size_t)z * Tc * Tc;
    const float* vb = g_v + (size_t)b * Tc * Dc + h * Ac;

    int ar = t >> 1, ac = (t & 1) * 4;        // A rows ar, ar+64
    int br = t >> 4, bc = (t & 15) * 4;       // B row br, cols bc..bc+3
    const float* Aptr0 = ap + (size_t)(q0 + ar) * Tc + ac;
    const float* Aptr1 = ap + (size_t)(q0 + ar + 64) * Tc + ac;
    const float* Bptr  = vb + (size_t)br * Dc + bc;

    int tx = t & 7, ty = t >> 3;              // 8 x 16 thread grid
    float acc[8][8] = {};

    float4 pa0 = *(const float4*)Aptr0;
    float4 pa1 = *(const float4*)Aptr1;
    float4 pb  = *(const float4*)Bptr;

    for (int k0 = 0; k0 < Tc; k0 += 8) {
        As[ac + 0][ar] = pa0.x; As[ac + 1][ar] = pa0.y;
        As[ac + 2][ar] = pa0.z; As[ac + 3][ar] = pa0.w;
        As[ac + 0][ar + 64] = pa1.x; As[ac + 1][ar + 64] = pa1.y;
        As[ac + 2][ar + 64] = pa1.z; As[ac + 3][ar + 64] = pa1.w;
        *(float4*)&Bs[br][bc] = pb;
        __syncthreads();
        if (k0 + 8 < Tc) {
            pa0 = *(const float4*)(Aptr0 + k0 + 8);
            pa1 = *(const float4*)(Aptr1 + k0 + 8);
            pb  = *(const float4*)(Bptr + (size_t)(k0 + 8) * Dc);
        }
        #pragma unroll
        for (int kk = 0; kk < 8; kk++) {
            float4 a0v = *(const float4*)&As[kk][ty * 4];
            float4 a1v = *(const float4*)&As[kk][ty * 4 + 64];
            float4 b0v = *(const float4*)&Bs[kk][tx * 4];
            float4 b1v = *(const float4*)&Bs[kk][tx * 4 + 32];
            float av[8] = {a0v.x,a0v.y,a0v.z,a0v.w,a1v.x,a1v.y,a1v.z,a1v.w};
            float bv[8] = {b0v.x,b0v.y,b0v.z,b0v.w,b1v.x,b1v.y,b1v.z,b1v.w};
            #pragma unroll
            for (int i = 0; i < 8; i++)
                #pragma unroll
                for (int j = 0; j < 8; j++)
                    acc[i][j] += av[i] * bv[j];
        }
        __syncthreads();
    }
    #pragma unroll
    for (int i = 0; i < 8; i++) {
        int qg = q0 + ty * 4 + (i & 3) + (i >> 2) * 64;
        float* crow = g_ctx + ((size_t)b * Tc + qg) * Dc + h * Ac;
        #pragma unroll
        for (int jh = 0; jh < 2; jh++) {
            int n = tx * 4 + jh * 32;
            *(float4*)(crow + n) = make_float4(acc[i][jh*4+0], acc[i][jh*4+1],
                                               acc[i][jh*4+2], acc[i][jh*4+3]);
        }
    }
}

// ---------------- host driver -----------------------------------------------
extern "C" void kernel_launch(void* const* d_in, const int* in_sizes, int n_in,
                              void* d_out, int out_size)
{
    const int*   tokens = (const int*)  d_in[0];
    const float* masks  = (const float*)d_in[1];
    const int*   ab     = (const int*)  d_in[2];
    const float* embed  = (const float*)d_in[3];
    const float* Wq     = (const float*)d_in[4];
    const float* Wk     = (const float*)d_in[5];
    const float* Wv     = (const float*)d_in[6];
    const float* Wo     = (const float*)d_in[7];
    const float* be     = (const float*)d_in[8];
    const float* bs     = (const float*)d_in[9];
    const float* ln_g   = (const float*)d_in[10];
    const float* ln_b   = (const float*)d_in[11];
    const float* ff1w   = (const float*)d_in[12];
    const float* ff1b   = (const float*)d_in[13];
    const float* ff2w   = (const float*)d_in[14];
    const float* ff2b   = (const float*)d_in[15];
    const float* lng    = (const float*)d_in[16];
    const float* lnb    = (const float*)d_in[17];
    float* out = (float*)d_out;

    float *x, *h, *q, *k, *v, *ctx, *dense, *ffh;
    cudaGetSymbolAddress((void**)&x,     g_x);
    cudaGetSymbolAddress((void**)&h,     g_h);
    cudaGetSymbolAddress((void**)&q,     g_q);
    cudaGetSymbolAddress((void**)&k,     g_k);
    cudaGetSymbolAddress((void**)&v,     g_v);
    cudaGetSymbolAddress((void**)&ctx,   g_ctx);
    cudaGetSymbolAddress((void**)&dense, g_dense);
    cudaGetSymbolAddress((void**)&ffh,   g_ffh);

    const int MT = Bc * Tc;                 // 8192 tokens

    embed_pe_kernel<<<MT, 512>>>(tokens, embed);

    for (int l = 0; l < Lc; l++) {
        const float* Wq_l  = Wq + (size_t)l * Dc * Dc;
        const float* Wk_l  = Wk + (size_t)l * Dc * Dc;
        const float* Wv_l  = Wv + (size_t)l * Dc * Dc;
        const float* Wo_l  = Wo + (size_t)l * Dc * Dc;
        const float* be_l  = be + (size_t)l * BIASDIM * Ac;
        const float* bs_l  = bs + (size_t)l * Ac;
        const float* ln1g  = ln_g + (size_t)l * 2 * Dc;
        const float* ln1b  = ln_b + (size_t)l * 2 * Dc;
        const float* ln2g  = ln1g + Dc;
        const float* ln2b  = ln1b + Dc;
        const float* f1w   = ff1w + (size_t)l * Dc * Fc;
        const float* f1b   = ff1b + (size_t)l * Fc;
        const float* f2w   = ff2w + (size_t)l * Fc * Dc;
        const float* f2b   = ff2b + (size_t)l * Dc;

        // LN1
        layernorm_kernel<<<MT, 256>>>(x, ln1g, ln1b, h);

        // QKV projections
        gemm_nn_128<<<dim3(Dc/128, MT/128), 256>>>(h, Wq_l, nullptr, nullptr, q, MT, Dc, Dc, 0);
        gemm_nn_128<<<dim3(Dc/128, MT/128), 256>>>(h, Wk_l, nullptr, nullptr, k, MT, Dc, Dc, 0);
        gemm_nn_128<<<dim3(Dc/128, MT/128), 256>>>(h, Wv_l, nullptr, nullptr, v, MT, Dc, Dc, 0);

        // ksum over a (transposed output [b,h,t])
        ksum_kernel<<<(Bc*Tc*Hc + 255)/256, 256>>>();

        // dense bias map: zero + scatter
        zero_kernel<<<(Bc*Tc*Tc/4 + 255)/256, 256>>>(dense, Bc*Tc*Tc/4);
        bias_scatter_kernel<<<(Ec + 255)/256, 256>>>(ab, be_l, bs_l);

        // scores + bias + scale + mask, then softmax
        attn_score_kernel<<<dim3(Tc/128, Tc/128, Bc*Hc), 256>>>(masks);
        softmax_kernel<<<Bc*Hc*Tc, 128>>>();

        // context, output projection + residual
        attn_ctx_kernel<<<dim3(Tc/128, Bc*Hc), 128>>>();
        gemm_nn_128<<<dim3(Dc/128, MT/128), 256>>>(ctx, Wo_l, nullptr, x, x, MT, Dc, Dc, 0);

        // LN2 + FFN + residual
        layernorm_kernel<<<MT, 256>>>(x, ln2g, ln2b, h);
        gemm_nn_128<<<dim3(Fc/128, MT/128), 256>>>(h, f1w, f1b, nullptr, ffh, MT, Fc, Dc, 1);
        gemm_nn_128<<<dim3(Dc/128, MT/128), 256>>>(ffh, f2w, f2b, x, x, MT, Dc, Fc, 0);
    }

    // final layernorm -> output
    layernorm_kernel<<<MT, 256>>>(x, lng, lnb, out);
}